// round 2
// baseline (speedup 1.0000x reference)
#include <cuda_runtime.h>
#include <cstdint>
#include <cstddef>

// ---------------------------------------------------------------------------
// DecP: PointNet++ decoder
//   4x { propagate(3-NN interp + concat) -> 1x1 conv GEMM -> global BN + ReLU }
//   then dec0 GEMM + BN + ReLU, then dec1 (O=1) dot.
// Round 1: fp32 SIMT baseline; FIXED input mapping (size-based assignment —
// setup_inputs interleaves xyz{i}/x{i}).
// ---------------------------------------------------------------------------

#define NBATCH 16

// Scratch (allocation-free rule: __device__ globals). Max tensor: 16x1984x2048.
__device__ float g_bufA[(size_t)NBATCH * 1984 * 2048];
__device__ float g_bufB[(size_t)NBATCH * 1984 * 2048];
__device__ int   g_idx [(size_t)NBATCH * 2048 * 3];
__device__ float g_wgt [(size_t)NBATCH * 2048 * 3];

// ---------------------------------------------------------------------------
// KNN (k=3) with inverse-distance weights.
// Matches reference: d = |a|^2 + |b|^2 - 2 a.b ; top_k tie-break = lower index.
// ---------------------------------------------------------------------------
__global__ void knn_kernel(const float* __restrict__ xyzq,   // (B, N1, 3)
                           const float* __restrict__ xyzs,   // (B, S, 3)
                           int N1, int S,
                           int* __restrict__ idx_out,        // (B, N1, 3)
                           float* __restrict__ w_out)        // (B, N1, 3)
{
    __shared__ float sx[512], sy[512], sz[512], sn[512];
    int b = blockIdx.y;
    for (int i = threadIdx.x; i < S; i += blockDim.x) {
        float X = xyzs[((size_t)b * S + i) * 3 + 0];
        float Y = xyzs[((size_t)b * S + i) * 3 + 1];
        float Z = xyzs[((size_t)b * S + i) * 3 + 2];
        sx[i] = X; sy[i] = Y; sz[i] = Z;
        sn[i] = X * X + Y * Y + Z * Z;
    }
    __syncthreads();

    int n = blockIdx.x * blockDim.x + threadIdx.x;
    if (n >= N1) return;

    float x = xyzq[((size_t)b * N1 + n) * 3 + 0];
    float y = xyzq[((size_t)b * N1 + n) * 3 + 1];
    float z = xyzq[((size_t)b * N1 + n) * 3 + 2];
    float nq = x * x + y * y + z * z;

    float d0 = 3.4e38f, d1 = 3.4e38f, d2 = 3.4e38f;
    int   i0 = 0, i1 = 0, i2 = 0;
    for (int s = 0; s < S; s++) {
        float d = nq + sn[s] - 2.0f * (x * sx[s] + y * sy[s] + z * sz[s]);
        if (d < d0)      { d2 = d1; i2 = i1; d1 = d0; i1 = i0; d0 = d; i0 = s; }
        else if (d < d1) { d2 = d1; i2 = i1; d1 = d;  i1 = s; }
        else if (d < d2) { d2 = d;  i2 = s; }
    }
    float w0 = 1.0f / (d0 + 1e-8f);
    float w1 = 1.0f / (d1 + 1e-8f);
    float w2 = 1.0f / (d2 + 1e-8f);
    float ws = w0 + w1 + w2;
    size_t o = ((size_t)b * N1 + n) * 3;
    idx_out[o + 0] = i0; idx_out[o + 1] = i1; idx_out[o + 2] = i2;
    w_out[o + 0] = w0 / ws; w_out[o + 1] = w1 / ws; w_out[o + 2] = w2 / ws;
}

// ---------------------------------------------------------------------------
// Interp + concat:
// out[b, c, n]       = p1[b, c, n]                         for c < C1
// out[b, C1+c2, n]   = sum_j w[b,n,j] * p2[b, c2, idx[b,n,j]]
// ---------------------------------------------------------------------------
__global__ void interp_concat_kernel(const float* __restrict__ p1,  // (B, C1, N1)
                                     const float* __restrict__ p2,  // (B, C2, S)
                                     const int* __restrict__ idx,
                                     const float* __restrict__ wgt,
                                     float* __restrict__ out,       // (B, C1+C2, N1)
                                     int C1, int C2, int N1, int S)
{
    int C = C1 + C2;
    size_t t = (size_t)blockIdx.x * blockDim.x + threadIdx.x;
    size_t total = (size_t)NBATCH * C * N1;
    if (t >= total) return;
    int n = (int)(t % N1);
    int c = (int)((t / N1) % C);
    int b = (int)(t / ((size_t)N1 * C));
    if (c < C1) {
        out[t] = p1[((size_t)b * C1 + c) * N1 + n];
    } else {
        int c2 = c - C1;
        size_t q = ((size_t)b * N1 + n) * 3;
        const float* p2r = p2 + ((size_t)b * C2 + c2) * S;
        out[t] = wgt[q + 0] * p2r[idx[q + 0]]
               + wgt[q + 1] * p2r[idx[q + 1]]
               + wgt[q + 2] * p2r[idx[q + 2]];
    }
}

// ---------------------------------------------------------------------------
// Batched fp32 GEMM: Y[b] = W (OxC) @ X[b] (CxN), b = blockIdx.z
// 64x64 tile, 16-deep K, 4x4 per thread. C is always a multiple of 16.
// ---------------------------------------------------------------------------
#define GT 64
#define GK 16
#define GP 68   // padded row (GP*4 bytes = 272, 16B-aligned rows)

__global__ void gemm_kernel(const float* __restrict__ W,   // (O, C) row-major
                            const float* __restrict__ X,   // (B, C, N)
                            float* __restrict__ Y,         // (B, O, N)
                            int O, int C, int N)
{
    __shared__ float As[GK][GP];  // As[k][o]
    __shared__ float Bs[GK][GP];  // Bs[k][n]
    int b = blockIdx.z;
    const float* Xb = X + (size_t)b * C * N;
    float*       Yb = Y + (size_t)b * O * N;

    int tx = threadIdx.x;            // 0..15 -> n
    int ty = threadIdx.y;            // 0..15 -> o
    int tid = ty * 16 + tx;
    int o0 = blockIdx.y * GT;
    int n0 = blockIdx.x * GT;

    float acc[4][4] = {};

    for (int k0 = 0; k0 < C; k0 += GK) {
        #pragma unroll
        for (int i = 0; i < 4; i++) {              // load W tile: 64x16
            int e = tid + i * 256;
            int o = e >> 4;
            int k = e & 15;
            As[k][o] = (o0 + o < O) ? W[(size_t)(o0 + o) * C + k0 + k] : 0.0f;
        }
        #pragma unroll
        for (int i = 0; i < 4; i++) {              // load X tile: 16x64
            int e = tid + i * 256;
            int k = e >> 6;
            int n = e & 63;
            Bs[k][n] = (n0 + n < N) ? Xb[(size_t)(k0 + k) * N + n0 + n] : 0.0f;
        }
        __syncthreads();
        #pragma unroll
        for (int k = 0; k < GK; k++) {
            float4 av = *reinterpret_cast<const float4*>(&As[k][ty * 4]);
            float4 bv = *reinterpret_cast<const float4*>(&Bs[k][tx * 4]);
            float a_[4] = {av.x, av.y, av.z, av.w};
            float b_[4] = {bv.x, bv.y, bv.z, bv.w};
            #pragma unroll
            for (int i = 0; i < 4; i++)
                #pragma unroll
                for (int j = 0; j < 4; j++)
                    acc[i][j] += a_[i] * b_[j];
        }
        __syncthreads();
    }

    #pragma unroll
    for (int i = 0; i < 4; i++) {
        int o = o0 + ty * 4 + i;
        if (o >= O) continue;
        #pragma unroll
        for (int j = 0; j < 4; j++) {
            int n = n0 + tx * 4 + j;
            if (n < N) Yb[(size_t)o * N + n] = acc[i][j];
        }
    }
}

// ---------------------------------------------------------------------------
// Global BatchNorm (mean/var over batch & points per channel) + ReLU, in-place.
// One block per channel.
// ---------------------------------------------------------------------------
__global__ void bn_relu_kernel(float* __restrict__ y,       // (B, C, N)
                               const float* __restrict__ gamma,
                               const float* __restrict__ beta,
                               int C, int N)
{
    int c = blockIdx.x;
    int cnt = NBATCH * N;
    float s = 0.0f, s2 = 0.0f;
    for (int i = threadIdx.x; i < cnt; i += blockDim.x) {
        int b = i / N, n = i - b * N;
        float v = y[((size_t)b * C + c) * N + n];
        s += v; s2 += v * v;
    }
    __shared__ float rs[256], rs2[256];
    rs[threadIdx.x] = s; rs2[threadIdx.x] = s2;
    __syncthreads();
    for (int st = 128; st > 0; st >>= 1) {
        if (threadIdx.x < st) {
            rs[threadIdx.x]  += rs[threadIdx.x + st];
            rs2[threadIdx.x] += rs2[threadIdx.x + st];
        }
        __syncthreads();
    }
    float mean = rs[0] / (float)cnt;
    float var  = rs2[0] / (float)cnt - mean * mean;
    float scale = gamma[c] * rsqrtf(var + 1e-5f);
    float shift = beta[c] - mean * scale;
    for (int i = threadIdx.x; i < cnt; i += blockDim.x) {
        int b = i / N, n = i - b * N;
        size_t q = ((size_t)b * C + c) * N + n;
        float v = y[q] * scale + shift;
        y[q] = v > 0.0f ? v : 0.0f;
    }
}

// ---------------------------------------------------------------------------
// dec1: out[b, n] = sum_c w[c] * x[b, c, n]   (O = 1)
// ---------------------------------------------------------------------------
__global__ void dec1_kernel(const float* __restrict__ x,    // (B, C, N)
                            const float* __restrict__ w,    // (C,)
                            float* __restrict__ out,        // (B, N)
                            int C, int N)
{
    int t = blockIdx.x * blockDim.x + threadIdx.x;
    if (t >= NBATCH * N) return;
    int b = t / N, n = t - b * N;
    const float* xb = x + (size_t)b * C * N + n;
    float acc = 0.0f;
    for (int c = 0; c < C; c++) acc += w[c] * xb[(size_t)c * N];
    out[t] = acc;
}

// ---------------------------------------------------------------------------
extern "C" void kernel_launch(void* const* d_in, const int* in_sizes, int n_in,
                              void* d_out, int out_size)
{
    // ---- Robust input assignment by element count ----
    // setup_inputs() interleaves xyz{i} / x{i}; all 10 sizes are distinct:
    //   xyz sizes: 16*npts*3 ; x sizes: 16*ch*npts
    const int npts[5] = {2048, 512, 128, 32, 8};
    const int chs [5] = {64, 128, 256, 512, 1024};
    const float* xyz[5] = {0, 0, 0, 0, 0};
    const float* xf [5] = {0, 0, 0, 0, 0};
    for (int i = 0; i < 10; i++) {
        int sz = in_sizes[i];
        for (int l = 0; l < 5; l++) {
            if (sz == NBATCH * npts[l] * 3)      xyz[l] = (const float*)d_in[i];
            else if (sz == NBATCH * chs[l] * npts[l]) xf[l] = (const float*)d_in[i];
        }
    }
    // Weights follow in declaration order after the first 10 inputs.
    const float* w_lin[4] = {(const float*)d_in[10], (const float*)d_in[13],
                             (const float*)d_in[16], (const float*)d_in[19]};
    const float* g_lin[4] = {(const float*)d_in[11], (const float*)d_in[14],
                             (const float*)d_in[17], (const float*)d_in[20]};
    const float* b_lin[4] = {(const float*)d_in[12], (const float*)d_in[15],
                             (const float*)d_in[18], (const float*)d_in[21]};
    const float* w_dec0 = (const float*)d_in[22];
    const float* g_dec  = (const float*)d_in[23];
    const float* b_dec  = (const float*)d_in[24];
    const float* w_dec1 = (const float*)d_in[25];
    float* out = (float*)d_out;

    float *A, *Bf; int *idx; float *wgt;
    cudaGetSymbolAddress((void**)&A,   g_bufA);
    cudaGetSymbolAddress((void**)&Bf,  g_bufB);
    cudaGetSymbolAddress((void**)&idx, g_idx);
    cudaGetSymbolAddress((void**)&wgt, g_wgt);

    // Stage tables.
    //   stage i: propagate(xyz[3-i], xyz[4-i], p1=x[3-i], p2)
    const int   N1s[4] = {32, 128, 512, 2048};
    const int   Ss [4] = {8, 32, 128, 512};
    const int   C1s[4] = {512, 256, 128, 64};
    const int   C2s[4] = {1024, 1536, 1792, 1920};
    const float* qxyz[4] = {xyz[3], xyz[2], xyz[1], xyz[0]};
    const float* sxyz[4] = {xyz[4], xyz[3], xyz[2], xyz[1]};
    const float* p1s [4] = {xf[3], xf[2], xf[1], xf[0]};

    for (int i = 0; i < 4; i++) {
        int N1 = N1s[i], S = Ss[i], C1 = C1s[i], C2 = C2s[i];
        int Cc = C1 + C2;               // == O of this stage's GEMM
        const float* p2 = (i == 0) ? xf[4] : Bf;

        knn_kernel<<<dim3((N1 + 255) / 256, NBATCH), 256>>>(
            qxyz[i], sxyz[i], N1, S, idx, wgt);

        size_t total = (size_t)NBATCH * Cc * N1;
        interp_concat_kernel<<<(unsigned)((total + 255) / 256), 256>>>(
            p1s[i], p2, idx, wgt, A, C1, C2, N1, S);

        gemm_kernel<<<dim3((N1 + GT - 1) / GT, (Cc + GT - 1) / GT, NBATCH),
                      dim3(16, 16)>>>(w_lin[i], A, Bf, Cc, Cc, N1);

        bn_relu_kernel<<<Cc, 256>>>(Bf, g_lin[i], b_lin[i], Cc, N1);
    }

    // dec0: (256 x 1984) @ (16, 1984, 2048) -> A
    gemm_kernel<<<dim3(2048 / GT, 256 / GT, NBATCH), dim3(16, 16)>>>(
        w_dec0, Bf, A, 256, 1984, 2048);
    bn_relu_kernel<<<256, 256>>>(A, g_dec, b_dec, 256, 2048);

    // dec1: (1 x 256) @ (16, 256, 2048) -> out (16, 2048)
    dec1_kernel<<<(NBATCH * 2048 + 255) / 256, 256>>>(A, w_dec1, out, 256, 2048);
}

// round 5
// speedup vs baseline: 2.7516x; 2.7516x over previous
#include <cuda_runtime.h>
#include <cuda_bf16.h>
#include <cstdint>
#include <cstddef>

// ===========================================================================
// DecP on GB300 (sm_103 portable path): mma.sync bf16 split-precision GEMMs.
// Activations as (M = B*npts, 2C) row-major bf16 hi|lo. 3 MMA passes:
// hi*Whi + lo*Whi + hi*Wlo, fp32 register accumulators.
// ===========================================================================

#define NBATCH 16

// ---------------- device scratch (allocation-free rule) --------------------
__device__ __align__(16) __nv_bfloat16 g_act [(size_t)32768 * 3968];
__device__ __align__(16) float         g_gemm[(size_t)32768 * 1984];
__device__ __align__(16) __nv_bfloat16 g_ws  [(size_t)27402240];
__device__ int   g_idx [(size_t)32768 * 3];
__device__ float g_wgt [(size_t)32768 * 3];
__device__ float g_ps  [(size_t)256 * 1984];
__device__ float g_ps2 [(size_t)256 * 1984];
__device__ float g_scale[1984];
__device__ float g_shift[1984];

// ---------------- PTX helpers ----------------------------------------------
__device__ __forceinline__ uint32_t smem_u32(const void* p) {
    uint32_t a;
    asm("{ .reg .u64 t; cvta.to.shared.u64 t, %1; cvt.u32.u64 %0, t; }"
        : "=r"(a) : "l"(p));
    return a;
}
#define CP_ASYNC(dst, src, sz) \
    asm volatile("cp.async.cg.shared.global [%0], [%1], 16, %2;" \
                 :: "r"(dst), "l"(src), "r"(sz) : "memory")
#define CP_COMMIT() asm volatile("cp.async.commit_group;" ::: "memory")
#define CP_WAIT(n)  asm volatile("cp.async.wait_group %0;" :: "n"(n) : "memory")

__device__ __forceinline__ void ldsm4(uint32_t* r, uint32_t addr) {
    asm volatile("ldmatrix.sync.aligned.m8n8.x4.shared.b16 {%0,%1,%2,%3}, [%4];"
                 : "=r"(r[0]), "=r"(r[1]), "=r"(r[2]), "=r"(r[3]) : "r"(addr));
}
__device__ __forceinline__ void mma16816(float* c, const uint32_t* a,
                                         uint32_t b0, uint32_t b1) {
    asm volatile(
        "mma.sync.aligned.m16n8k16.row.col.f32.bf16.bf16.f32 "
        "{%0,%1,%2,%3}, {%4,%5,%6,%7}, {%8,%9}, {%0,%1,%2,%3};"
        : "+f"(c[0]), "+f"(c[1]), "+f"(c[2]), "+f"(c[3])
        : "r"(a[0]), "r"(a[1]), "r"(a[2]), "r"(a[3]), "r"(b0), "r"(b1));
}

// ---------------------------------------------------------------------------
// GEMM: D(M,Nglob) fp32 = A(M,2C) . W(Nglob,2C)^T over 3 split passes.
// CTA tile 128x128, K-chunk 64 bf16 (128B swizzled rows), cp.async 2-stage.
// ---------------------------------------------------------------------------
#define BM 128
#define BN 128
#define STAGE_BYTES (BM * 128 + BN * 128)       // 32 KB
#define GEMM_SMEM   (2 * STAGE_BYTES + 1024)    // + alignment slack

__global__ void __launch_bounds__(256, 2)
gemm_bf16_kernel(const __nv_bfloat16* __restrict__ Act,
                 const __nv_bfloat16* __restrict__ Wsp,
                 float* __restrict__ Y,
                 int M, int Nglob, int C)        // KA = 2C
{
    extern __shared__ char smem[];
    uint32_t sb = (smem_u32(smem) + 1023u) & ~1023u;

    int tid = threadIdx.x, wid = tid >> 5, lane = tid & 31;
    int m0 = blockIdx.y * BM;
    int n0 = blockIdx.x * BN;
    int nvalid = Nglob - n0; if (nvalid > BN) nvalid = BN;
    int KA = 2 * C;
    int nch = C >> 6;
    int NC = 3 * nch;

    int mw = (wid >> 1) * 32;     // warp tile: rows [mw, mw+32)
    int nw = (wid & 1) * 64;      //            cols [nw, nw+64)

    float acc[2][8][4];
    #pragma unroll
    for (int i = 0; i < 2; i++)
        #pragma unroll
        for (int j = 0; j < 8; j++)
            #pragma unroll
            for (int e = 0; e < 4; e++) acc[i][j][e] = 0.0f;

    // ---- async tile loader -------------------------------------------------
    auto issue = [&](int ci) {
        int p  = ci / nch;
        int kc = ci - p * nch;
        int ka = ((p == 1) ? C : 0) + (kc << 6);     // A seg offset (elems)
        int kb = ((p == 2) ? C : 0) + (kc << 6);     // W seg offset
        uint32_t s = sb + (uint32_t)(ci & 1) * STAGE_BYTES;
        // A: 128 rows x 8 x 16B
        #pragma unroll
        for (int it = 0; it < 4; it++) {
            int idx = tid + it * 256;
            int r = idx >> 3, u = idx & 7;
            uint32_t dst = s + (uint32_t)(r * 128 + ((u ^ (r & 7)) << 4));
            const void* src = Act + (size_t)(m0 + r) * KA + ka + u * 8;
            CP_ASYNC(dst, src, 16);
        }
        // B: 128 rows x 8 x 16B, zero-fill rows past Nglob
        uint32_t sB = s + BM * 128;
        #pragma unroll
        for (int it = 0; it < 4; it++) {
            int idx = tid + it * 256;
            int r = idx >> 3, u = idx & 7;
            int rv = r < nvalid ? r : (nvalid - 1);
            int sz = r < nvalid ? 16 : 0;
            uint32_t dst = sB + (uint32_t)(r * 128 + ((u ^ (r & 7)) << 4));
            const void* src = Wsp + (size_t)(n0 + rv) * KA + kb + u * 8;
            CP_ASYNC(dst, src, sz);
        }
        CP_COMMIT();
    };

    issue(0);
    for (int ci = 0; ci < NC; ci++) {
        if (ci + 1 < NC) { issue(ci + 1); CP_WAIT(1); }
        else             { CP_WAIT(0); }
        __syncthreads();

        uint32_t sA = sb + (uint32_t)(ci & 1) * STAGE_BYTES;
        uint32_t sB = sA + BM * 128;
        #pragma unroll
        for (int ks = 0; ks < 4; ks++) {
            uint32_t a[2][4];
            #pragma unroll
            for (int i = 0; i < 2; i++) {
                int r = mw + i * 16 + (lane & 15);
                int u = ks * 2 + (lane >> 4);
                ldsm4(a[i], sA + (uint32_t)(r * 128 + ((u ^ (r & 7)) << 4)));
            }
            uint32_t bfr[4][4];
            #pragma unroll
            for (int jj = 0; jj < 4; jj++) {
                int r = nw + jj * 16 + (lane & 15);
                int u = ks * 2 + (lane >> 4);
                ldsm4(bfr[jj], sB + (uint32_t)(r * 128 + ((u ^ (r & 7)) << 4)));
            }
            #pragma unroll
            for (int i = 0; i < 2; i++)
                #pragma unroll
                for (int jj = 0; jj < 4; jj++) {
                    mma16816(acc[i][2 * jj],     a[i], bfr[jj][0], bfr[jj][2]);
                    mma16816(acc[i][2 * jj + 1], a[i], bfr[jj][1], bfr[jj][3]);
                }
        }
        __syncthreads();
    }

    // ---- epilogue: direct fp32 stores -------------------------------------
    int lr = lane >> 2;           // 0..7
    int lc = (lane & 3) * 2;      // 0,2,4,6
    #pragma unroll
    for (int i = 0; i < 2; i++) {
        int row = m0 + mw + i * 16 + lr;
        #pragma unroll
        for (int j = 0; j < 8; j++) {
            int col = n0 + nw + j * 8 + lc;
            if (col < Nglob) {
                float2 v0 = make_float2(acc[i][j][0], acc[i][j][1]);
                float2 v1 = make_float2(acc[i][j][2], acc[i][j][3]);
                *(float2*)(Y + (size_t)row * Nglob + col)       = v0;
                *(float2*)(Y + (size_t)(row + 8) * Nglob + col) = v1;
            }
        }
    }
}

// ---------------------------------------------------------------------------
// KNN (k=3), inverse-distance weights. Matches reference formula + tie-break.
// ---------------------------------------------------------------------------
__global__ void knn_kernel(const float* __restrict__ xyzq, const float* __restrict__ xyzs,
                           int N1, int S, int* __restrict__ idx_out, float* __restrict__ w_out)
{
    __shared__ float sx[512], sy[512], sz[512], sn[512];
    int b = blockIdx.y;
    for (int i = threadIdx.x; i < S; i += blockDim.x) {
        float X = xyzs[((size_t)b * S + i) * 3 + 0];
        float Y = xyzs[((size_t)b * S + i) * 3 + 1];
        float Z = xyzs[((size_t)b * S + i) * 3 + 2];
        sx[i] = X; sy[i] = Y; sz[i] = Z; sn[i] = X * X + Y * Y + Z * Z;
    }
    __syncthreads();
    int n = blockIdx.x * blockDim.x + threadIdx.x;
    if (n >= N1) return;
    float x = xyzq[((size_t)b * N1 + n) * 3 + 0];
    float y = xyzq[((size_t)b * N1 + n) * 3 + 1];
    float z = xyzq[((size_t)b * N1 + n) * 3 + 2];
    float nq = x * x + y * y + z * z;
    float d0 = 3.4e38f, d1 = 3.4e38f, d2 = 3.4e38f;
    int   i0 = 0, i1 = 0, i2 = 0;
    for (int s = 0; s < S; s++) {
        float d = nq + sn[s] - 2.0f * (x * sx[s] + y * sy[s] + z * sz[s]);
        if (d < d0)      { d2 = d1; i2 = i1; d1 = d0; i1 = i0; d0 = d; i0 = s; }
        else if (d < d1) { d2 = d1; i2 = i1; d1 = d;  i1 = s; }
        else if (d < d2) { d2 = d;  i2 = s; }
    }
    float w0 = 1.0f / (d0 + 1e-8f), w1 = 1.0f / (d1 + 1e-8f), w2 = 1.0f / (d2 + 1e-8f);
    float ws = w0 + w1 + w2;
    size_t o = ((size_t)b * N1 + n) * 3;
    idx_out[o] = i0; idx_out[o + 1] = i1; idx_out[o + 2] = i2;
    w_out[o] = w0 / ws; w_out[o + 1] = w1 / ws; w_out[o + 2] = w2 / ws;
}

// ---------------------------------------------------------------------------
// Interp + concat + bf16 split -> g_act (M, 2C). Block = point m.
// ---------------------------------------------------------------------------
__global__ void interp_split_kernel(const float* __restrict__ p1, const float* __restrict__ p2,
                                    const int* __restrict__ idx, const float* __restrict__ wgt,
                                    __nv_bfloat16* __restrict__ out,
                                    int C1, int C2, int N1,
                                    long sb2, long ss2, long sc2)
{
    int m = blockIdx.x;
    int b = m / N1, n = m - b * N1;
    int C = C1 + C2;
    size_t q = (size_t)m * 3;
    int i0 = idx[q], i1 = idx[q + 1], i2 = idx[q + 2];
    float w0 = wgt[q], w1 = wgt[q + 1], w2 = wgt[q + 2];
    const float* r0 = p2 + (size_t)b * sb2 + (size_t)i0 * ss2;
    const float* r1 = p2 + (size_t)b * sb2 + (size_t)i1 * ss2;
    const float* r2 = p2 + (size_t)b * sb2 + (size_t)i2 * ss2;
    __nv_bfloat16* orow = out + (size_t)m * 2 * C;
    for (int c = threadIdx.x; c < C; c += blockDim.x) {
        float v;
        if (c < C1) v = p1[((size_t)b * C1 + c) * N1 + n];
        else {
            size_t cc = (size_t)(c - C1) * sc2;
            v = w0 * r0[cc] + w1 * r1[cc] + w2 * r2[cc];
        }
        __nv_bfloat16 hi = __float2bfloat16(v);
        float lo = v - __bfloat162float(hi);
        orow[c]     = hi;
        orow[C + c] = __float2bfloat16(lo);
    }
}

// ---------------------------------------------------------------------------
// Weight split: (O, C) fp32 -> (O, 2C) bf16 hi|lo
// ---------------------------------------------------------------------------
__global__ void wsplit_kernel(const float* __restrict__ w, __nv_bfloat16* __restrict__ out,
                              int O, int C)
{
    int t = blockIdx.x * blockDim.x + threadIdx.x;
    if (t >= O * C) return;
    int o = t / C, c = t - o * C;
    float v = w[t];
    __nv_bfloat16 hi = __float2bfloat16(v);
    float lo = v - __bfloat162float(hi);
    out[(size_t)o * 2 * C + c]     = hi;
    out[(size_t)o * 2 * C + C + c] = __float2bfloat16(lo);
}

// ---------------------------------------------------------------------------
// Deterministic BN: partial (128 rows/block), finalize, apply.
// ---------------------------------------------------------------------------
__global__ void bn_partial_kernel(const float* __restrict__ Y,
                                  float* __restrict__ ps, float* __restrict__ ps2, int N)
{
    int n = blockIdx.x * 256 + threadIdx.x;
    if (n >= N) return;
    int mb = blockIdx.y;
    const float* p = Y + (size_t)mb * 128 * N + n;
    float s = 0.0f, s2 = 0.0f;
    #pragma unroll 4
    for (int r = 0; r < 128; r++) {
        float v = p[(size_t)r * N];
        s += v; s2 += v * v;
    }
    ps [(size_t)mb * N + n] = s;
    ps2[(size_t)mb * N + n] = s2;
}

__global__ void bn_finalize_kernel(const float* __restrict__ ps, const float* __restrict__ ps2,
                                   const float* __restrict__ g, const float* __restrict__ bta,
                                   float* __restrict__ scale, float* __restrict__ shift,
                                   int MB, int M, int N)
{
    int n = blockIdx.x * 256 + threadIdx.x;
    if (n >= N) return;
    float s = 0.0f, s2 = 0.0f;
    for (int mb = 0; mb < MB; mb++) { s += ps[(size_t)mb * N + n]; s2 += ps2[(size_t)mb * N + n]; }
    float inv = 1.0f / (float)M;
    float mean = s * inv;
    float var = s2 * inv - mean * mean;
    float sc = g[n] * rsqrtf(var + 1e-5f);
    scale[n] = sc;
    shift[n] = bta[n] - mean * sc;
}

__global__ void bn_apply_kernel(float* __restrict__ Y, const float* __restrict__ scale,
                                const float* __restrict__ shift, size_t total, int N)
{
    size_t t = (size_t)blockIdx.x * blockDim.x + threadIdx.x;
    if (t >= total) return;
    int n = (int)(t % N);
    float v = Y[t] * scale[n] + shift[n];
    Y[t] = v > 0.0f ? v : 0.0f;
}

__global__ void bn_apply_split_kernel(const float* __restrict__ Y, const float* __restrict__ scale,
                                      const float* __restrict__ shift,
                                      __nv_bfloat16* __restrict__ out, size_t total, int N)
{
    size_t t = (size_t)blockIdx.x * blockDim.x + threadIdx.x;
    if (t >= total) return;
    size_t m = t / N;
    int n = (int)(t - m * N);
    float v = Y[t] * scale[n] + shift[n];
    v = v > 0.0f ? v : 0.0f;
    __nv_bfloat16 hi = __float2bfloat16(v);
    float lo = v - __bfloat162float(hi);
    out[m * 2 * N + n]     = hi;
    out[m * 2 * N + N + n] = __float2bfloat16(lo);
}

// ---------------------------------------------------------------------------
// dec1: out[m] = sum_c X[m][c] * w[c], warp per row
// ---------------------------------------------------------------------------
__global__ void dec1_kernel(const float* __restrict__ X, const float* __restrict__ w,
                            float* __restrict__ out, int M, int C)
{
    int gt = blockIdx.x * blockDim.x + threadIdx.x;
    int warp = gt >> 5, lane = gt & 31;
    if (warp >= M) return;
    const float* row = X + (size_t)warp * C;
    float acc = 0.0f;
    for (int c = lane; c < C; c += 32) acc += row[c] * w[c];
    #pragma unroll
    for (int s = 16; s > 0; s >>= 1) acc += __shfl_xor_sync(0xFFFFFFFF, acc, s);
    if (lane == 0) out[warp] = acc;
}

// ---------------------------------------------------------------------------
extern "C" void kernel_launch(void* const* d_in, const int* in_sizes, int n_in,
                              void* d_out, int out_size)
{
    // ---- input assignment by element count (setup interleaves xyz{i}/x{i}) --
    const int npts[5] = {2048, 512, 128, 32, 8};
    const int chs [5] = {64, 128, 256, 512, 1024};
    const float* xyz[5] = {0,0,0,0,0};
    const float* xf [5] = {0,0,0,0,0};
    for (int i = 0; i < 10; i++) {
        int sz = in_sizes[i];
        for (int l = 0; l < 5; l++) {
            if (sz == NBATCH * npts[l] * 3)           xyz[l] = (const float*)d_in[i];
            else if (sz == NBATCH * chs[l] * npts[l]) xf[l]  = (const float*)d_in[i];
        }
    }
    const float* w_lin[4] = {(const float*)d_in[10], (const float*)d_in[13],
                             (const float*)d_in[16], (const float*)d_in[19]};
    const float* g_lin[4] = {(const float*)d_in[11], (const float*)d_in[14],
                             (const float*)d_in[17], (const float*)d_in[20]};
    const float* b_lin[4] = {(const float*)d_in[12], (const float*)d_in[15],
                             (const float*)d_in[18], (const float*)d_in[21]};
    const float* w_dec0 = (const float*)d_in[22];
    const float* g_dec  = (const float*)d_in[23];
    const float* b_dec  = (const float*)d_in[24];
    const float* w_dec1 = (const float*)d_in[25];
    float* out = (float*)d_out;

    __nv_bfloat16 *act, *ws; float *gm; int *idx;
    float *wgt, *ps, *ps2, *scale, *shift;
    cudaGetSymbolAddress((void**)&act,   g_act);
    cudaGetSymbolAddress((void**)&gm,    g_gemm);
    cudaGetSymbolAddress((void**)&ws,    g_ws);
    cudaGetSymbolAddress((void**)&idx,   g_idx);
    cudaGetSymbolAddress((void**)&wgt,   g_wgt);
    cudaGetSymbolAddress((void**)&ps,    g_ps);
    cudaGetSymbolAddress((void**)&ps2,   g_ps2);
    cudaGetSymbolAddress((void**)&scale, g_scale);
    cudaGetSymbolAddress((void**)&shift, g_shift);

    cudaFuncSetAttribute(gemm_bf16_kernel,
                         cudaFuncAttributeMaxDynamicSharedMemorySize, GEMM_SMEM);

    // split weight offsets (bf16 elems)
    const size_t WOFF[5] = {
        0,
        (size_t)1536 * 3072,
        (size_t)1536 * 3072 + (size_t)1792 * 3584,
        (size_t)1536 * 3072 + (size_t)1792 * 3584 + (size_t)1920 * 3840,
        (size_t)1536 * 3072 + (size_t)1792 * 3584 + (size_t)1920 * 3840 + (size_t)1984 * 3968
    };
    const float* wsrc[5] = {w_lin[0], w_lin[1], w_lin[2], w_lin[3], w_dec0};
    const int    wO [5]  = {1536, 1792, 1920, 1984, 256};
    const int    wC [5]  = {1536, 1792, 1920, 1984, 1984};
    for (int i = 0; i < 5; i++)
        wsplit_kernel<<<(wO[i] * wC[i] + 255) / 256, 256>>>(wsrc[i], ws + WOFF[i], wO[i], wC[i]);

    // stage tables
    const int N1s[4] = {32, 128, 512, 2048};
    const int Ss [4] = {8, 32, 128, 512};
    const int C1s[4] = {512, 256, 128, 64};
    const int C2s[4] = {1024, 1536, 1792, 1920};
    const float* qxyz[4] = {xyz[3], xyz[2], xyz[1], xyz[0]};
    const float* sxyz[4] = {xyz[4], xyz[3], xyz[2], xyz[1]};
    const float* p1s [4] = {xf[3], xf[2], xf[1], xf[0]};

    for (int i = 0; i < 4; i++) {
        int N1 = N1s[i], S = Ss[i], C1 = C1s[i], C2 = C2s[i];
        int C  = C1 + C2;                      // Cin == Cout
        int M  = NBATCH * N1;

        knn_kernel<<<dim3((N1 + 255) / 256, NBATCH), 256>>>(qxyz[i], sxyz[i], N1, S, idx, wgt);

        long sb2, ss2, sc2;
        const float* p2;
        if (i == 0) { p2 = xf[4]; sb2 = (long)C2 * S; ss2 = 1;  sc2 = S; }
        else        { p2 = gm;    sb2 = (long)S * C2; ss2 = C2; sc2 = 1; }

        interp_split_kernel<<<M, 256>>>(p1s[i], p2, idx, wgt, act, C1, C2, N1, sb2, ss2, sc2);

        gemm_bf16_kernel<<<dim3((C + BN - 1) / BN, M / BM), 256, GEMM_SMEM>>>(
            act, ws + WOFF[i], gm, M, C, C);

        bn_partial_kernel<<<dim3((C + 255) / 256, M / 128), 256>>>(gm, ps, ps2, C);
        bn_finalize_kernel<<<(C + 255) / 256, 256>>>(ps, ps2, g_lin[i], b_lin[i],
                                                     scale, shift, M / 128, M, C);
        size_t tot = (size_t)M * C;
        if (i < 3)
            bn_apply_kernel<<<(unsigned)((tot + 255) / 256), 256>>>(gm, scale, shift, tot, C);
        else
            bn_apply_split_kernel<<<(unsigned)((tot + 255) / 256), 256>>>(gm, scale, shift,
                                                                          act, tot, C);
    }

    // dec0: (32768, 1984) -> (32768, 256)
    gemm_bf16_kernel<<<dim3(256 / BN, 32768 / BM), 256, GEMM_SMEM>>>(
        act, ws + WOFF[4], gm, 32768, 256, 1984);
    bn_partial_kernel<<<dim3(1, 32768 / 128), 256>>>(gm, ps, ps2, 256);
    bn_finalize_kernel<<<1, 256>>>(ps, ps2, g_dec, b_dec, scale, shift, 256, 32768, 256);
    {
        size_t tot = (size_t)32768 * 256;
        bn_apply_kernel<<<(unsigned)((tot + 255) / 256), 256>>>(gm, scale, shift, tot, 256);
    }
    // dec1: warp per row
    dec1_kernel<<<(32768 * 32 + 255) / 256, 256>>>(gm, w_dec1, out, 32768, 256);
}